// round 15
// baseline (speedup 1.0000x reference)
#include <cuda_runtime.h>
#include <cuda_fp16.h>
#include <cstdint>

// ============================================================
// out[b,k,c] = softmax_m( tanh(e[b,m]·W1[k] + d[b,k]·W2[m]) ) · x[b,m,c]
// B=16, N=2048, D=128.
// Flash-style fused attention, mma.sync.m16n8k16 + ldmatrix + cp.async.
// tanh bounds scores in [-1,1] -> no online max rescaling needed.
// R14: cross-warp phase stagger — each 64-key chunk split into two 32-key
//      halves; warp-group A (wid 0-3) does half0->half1, group B (wid 4-7)
//      does half1->half0. Each SMSP hosts one A + one B warp, so exp (MUFU)
//      of one overlaps QK (tensor/LDS) of the other. S halves to 32 regs.
//      Base otherwise = R12 (best, 178.1us).
// ============================================================

#define DEVI __device__ __forceinline__

constexpr int B_ = 16, N_ = 2048, D_ = 128, F_ = 256;
constexpr int MT = 256;              // queries per CTA
constexpr int KT = 64;               // keys per chunk
constexpr int NCHUNK = N_ / KT;      // 32

// ---------------- device scratch -------------------------------------------
__device__ __half g_Qf[(size_t)B_ * N_ * F_];   // [b,k,256] = [W1[k] | d[b,k]]
__device__ __half g_Kf[(size_t)B_ * N_ * F_];   // [b,m,256] = [e[b,m] | W2[m]]
__device__ __half g_XT[(size_t)B_ * D_ * N_];   // [b,c,m]   = x[b,m,c]

// ---------------- SMEM layout (bytes), XOR-swizzled, no padding -------------
constexpr int SM_Q   = 0;
constexpr int QSIZE  = MT * 512;                // 131072
constexpr int KSTAGE = KT * 512;                // 32768
constexpr int SM_K   = SM_Q + QSIZE;
constexpr int XSTAGE = D_ * 128;                // 16384
constexpr int SM_X   = SM_K + 2 * KSTAGE;
constexpr int SMEM_TOTAL = SM_X + 2 * XSTAGE;   // 229376 (224 KB)

// ---------------- PTX helpers ----------------------------------------------
DEVI uint32_t smem_u32(const void* p) {
    uint32_t a;
    asm("{ .reg .u64 t; cvta.to.shared.u64 t, %1; cvt.u32.u64 %0, t; }" : "=r"(a) : "l"(p));
    return a;
}
DEVI float ex2f(float x) { float y; asm("ex2.approx.f32 %0,%1;" : "=f"(y) : "f"(x)); return y; }
DEVI float tanhf_hw(float x) { float y; asm("tanh.approx.f32 %0,%1;" : "=f"(y) : "f"(x)); return y; }

DEVI void cp_async16(uint32_t dst, const void* src) {
    asm volatile("cp.async.cg.shared.global [%0], [%1], 16;" :: "r"(dst), "l"(src) : "memory");
}
DEVI void cp_commit() { asm volatile("cp.async.commit_group;" ::: "memory"); }
DEVI void cp_wait0()  { asm volatile("cp.async.wait_group 0;" ::: "memory"); }
DEVI void cp_wait1()  { asm volatile("cp.async.wait_group 1;" ::: "memory"); }
DEVI void cp_wait2()  { asm volatile("cp.async.wait_group 2;" ::: "memory"); }

DEVI void ldsm4(uint32_t r[4], uint32_t addr) {
    asm volatile("ldmatrix.sync.aligned.m8n8.x4.shared.b16 {%0,%1,%2,%3}, [%4];"
                 : "=r"(r[0]), "=r"(r[1]), "=r"(r[2]), "=r"(r[3]) : "r"(addr));
}
DEVI void mma16816(float d[4], const uint32_t a[4], uint32_t b0, uint32_t b1) {
    asm volatile("mma.sync.aligned.m16n8k16.row.col.f32.f16.f16.f32 "
                 "{%0,%1,%2,%3}, {%4,%5,%6,%7}, {%8,%9}, {%0,%1,%2,%3};"
                 : "+f"(d[0]), "+f"(d[1]), "+f"(d[2]), "+f"(d[3])
                 : "r"(a[0]), "r"(a[1]), "r"(a[2]), "r"(a[3]), "r"(b0), "r"(b1));
}

DEVI uint32_t h2_as_u32(__half2 h) { uint32_t u; __builtin_memcpy(&u, &h, 4); return u; }

// w = exp(tanh(s) - 1) = 2^( log2e*(tanh(s) - 1) )   (shift-invariant weight)
DEVI float wfun(float s) {
    const float l2e = 1.4426950409f;
    float t = tanhf_hw(s);
    return ex2f(fmaf(t, l2e, -l2e));
}

// ---------------- merged prep: Qf/Kf, warp-per-row-half (coalesced) ---------
constexpr int QK_WARPS = B_ * N_ * 2;           // 65536

__global__ void prep_qk(const float* __restrict__ e, const float* __restrict__ d,
                        const float* __restrict__ W1, const float* __restrict__ W2) {
    int w    = (int)((blockIdx.x * blockDim.x + threadIdx.x) >> 5);
    int lane = threadIdx.x & 31;
    if (w >= QK_WARPS) return;
    int h = w & 1;
    int k = (w >> 1) & (N_ - 1);
    int b = w >> 12;
    const float4* qsrc;
    const float4* ksrc;
    if (h == 0) {
        qsrc = (const float4*)(W1 + (size_t)k * D_);
        ksrc = (const float4*)(e + ((size_t)(b * N_ + k)) * D_);
    } else {
        qsrc = (const float4*)(d + ((size_t)(b * N_ + k)) * D_);
        ksrc = (const float4*)(W2 + (size_t)k * D_);
    }
    float4 qv = qsrc[lane];
    float4 kv = ksrc[lane];
    uint2 qo = make_uint2(h2_as_u32(__floats2half2_rn(qv.x, qv.y)),
                          h2_as_u32(__floats2half2_rn(qv.z, qv.w)));
    uint2 ko = make_uint2(h2_as_u32(__floats2half2_rn(kv.x, kv.y)),
                          h2_as_u32(__floats2half2_rn(kv.z, kv.w)));
    size_t roff = ((size_t)(b * N_ + k)) * F_ + h * 128 + lane * 4;
    *(uint2*)(g_Qf + roff) = qo;
    *(uint2*)(g_Kf + roff) = ko;
}

// ---------------- prep: XT[b,c,m] = fp16(x[b,m,c]) --------------------------
__global__ void transpose_x(const float* __restrict__ x) {
    __shared__ float tile[32][33];
    int b = blockIdx.z;
    int m0 = blockIdx.x * 32, c0 = blockIdx.y * 32;
    int tx = threadIdx.x, ty = threadIdx.y;
#pragma unroll
    for (int i = 0; i < 4; i++)
        tile[ty + 8 * i][tx] = x[((size_t)(b * N_ + m0 + ty + 8 * i)) * D_ + c0 + tx];
    __syncthreads();
#pragma unroll
    for (int i = 0; i < 4; i++)
        g_XT[((size_t)(b * D_ + c0 + ty + 8 * i)) * N_ + m0 + tx] =
            __float2half_rn(tile[tx][ty + 8 * i]);
}

// ---------------- chunk loader: K (64x256) + XT (128x64), swizzled ----------
DEVI void load_chunk(int b, int m0, int stage, uint32_t sb, int tid) {
    const uint32_t stK = sb + SM_K + stage * KSTAGE;
    const uint32_t stX = sb + SM_X + stage * XSTAGE;
    const __half* kbase = g_Kf + ((size_t)(b * N_ + m0)) * F_;
#pragma unroll
    for (int i = 0; i < 8; i++) {
        int lin = tid + i * 256;          // 0..2047
        int row = lin >> 5;               // 0..63
        int ch  = lin & 31;
        cp_async16(stK + row * 512 + ((ch ^ (row & 7)) << 4),
                   kbase + (size_t)row * F_ + ch * 8);
    }
    const __half* xbase = g_XT + (size_t)b * D_ * N_ + m0;
#pragma unroll
    for (int i = 0; i < 4; i++) {
        int lin = tid + i * 256;          // 0..1023
        int row = lin >> 3;               // c: 0..127
        int ch  = lin & 7;
        cp_async16(stX + row * 128 + ((ch ^ (row & 7)) << 4),
                   xbase + (size_t)row * N_ + ch * 8);
    }
    cp_commit();
}

// ---------------- main fused attention kernel -------------------------------
__global__ void __launch_bounds__(256, 1) attn_kernel(float* __restrict__ out) {
    extern __shared__ __align__(1024) char smem[];
    const uint32_t sb = smem_u32(smem);
    const int tid = threadIdx.x;
    const int wid = tid >> 5;
    const int lane = tid & 31;
    const int b = blockIdx.y;
    const int k0 = blockIdx.x * MT;
    const int qb = wid * 32;             // this warp's 32 query rows (2 m-tiles)
    const int grp = wid >> 2;            // 0 = wid 0-3, 1 = wid 4-7 (per-SMSP pairing)

    // ---- issue Q (group0), chunk0 (group1), chunk1 (group2) ----
    {
        const __half* qbase = g_Qf + ((size_t)(b * N_ + k0)) * F_;
#pragma unroll
        for (int i = 0; i < 32; i++) {
            int lin = tid + i * 256;      // 0..8191
            int row = lin >> 5;           // 0..255
            int ch  = lin & 31;
            cp_async16(sb + SM_Q + row * 512 + ((ch ^ (row & 7)) << 4),
                       qbase + (size_t)row * F_ + ch * 8);
        }
        cp_commit();
    }
    load_chunk(b, 0, 0, sb, tid);
    load_chunk(b, KT, 1, sb, tid);

    float O[2][16][4];
#pragma unroll
    for (int t = 0; t < 2; t++)
#pragma unroll
        for (int i = 0; i < 16; i++) { O[t][i][0] = O[t][i][1] = O[t][i][2] = O[t][i][3] = 0.f; }
    float den[2][2] = {{0.f, 0.f}, {0.f, 0.f}};

    // ldmatrix lane maps (verified R7+).
    // A (Q): row = lane&15, col-half = lane>>4.
    // B (K/X): row = (lane&7)+((lane>>4)<<3), col-half = (lane>>3)&1.
    const int arow = lane & 15;
    const int ahi  = lane >> 4;
    const int brow = (lane & 7) + ((lane >> 4) << 3);
    const int bhi  = (lane >> 3) & 1;
    const int xl   = lane & 7;           // row&7 for BOTH maps (tile bases %16==0)
    const uint32_t qrow0 = sb + SM_Q + (qb + arow) * 512;
    const uint32_t qrow1 = qrow0 + 16 * 512;

    cp_wait2();                           // Q group complete
    __syncthreads();

    for (int j = 0; j < NCHUNK; j++) {
        if (j + 1 < NCHUNK) cp_wait1(); else cp_wait0();
        __syncthreads();
        const uint32_t stK = sb + SM_K + (j & 1) * KSTAGE;
        const uint32_t stX = sb + SM_X + (j & 1) * XSTAGE;
        const uint32_t krow = stK + brow * 512;
        const uint32_t xrow = stX + brow * 128;

        // ---- two 32-key halves; group A: h=0,1  group B: h=1,0 ----
#pragma unroll
        for (int hh = 0; hh < 2; hh++) {
            const int h = hh ^ grp;

            // QK: S[32 x 32] = Q @ K(keys 32h..32h+31)^T
            float S[2][4][4];
#pragma unroll
            for (int t = 0; t < 2; t++)
#pragma unroll
                for (int i = 0; i < 4; i++) { S[t][i][0] = S[t][i][1] = S[t][i][2] = S[t][i][3] = 0.f; }

#pragma unroll
            for (int kt = 0; kt < 16; kt++) {
                const uint32_t cswA = (uint32_t)(((kt * 2 + ahi) ^ xl) << 4);
                const uint32_t cswB = (uint32_t)(((kt * 2 + bhi) ^ xl) << 4);
                uint32_t qa0[4], qa1[4];
                ldsm4(qa0, qrow0 + cswA);
                ldsm4(qa1, qrow1 + cswA);
#pragma unroll
                for (int g = 0; g < 2; g++) {
                    const int ng = 2 * h + g;
                    uint32_t kb[4];
                    ldsm4(kb, krow + ng * 16 * 512 + cswB);
                    mma16816(S[0][2 * g],     qa0, kb[0], kb[1]);
                    mma16816(S[0][2 * g + 1], qa0, kb[2], kb[3]);
                    mma16816(S[1][2 * g],     qa1, kb[0], kb[1]);
                    mma16816(S[1][2 * g + 1], qa1, kb[2], kb[3]);
                }
            }

            // exp + PV for the two 16-key groups of this half
#pragma unroll
            for (int g = 0; g < 2; g++) {
                const int t2 = 2 * h + g;      // global 16-key group (X m-chunk)
                uint32_t Pf[2][4];
#pragma unroll
                for (int t = 0; t < 2; t++) {
                    int j0 = 2 * g, j1 = 2 * g + 1;
                    __half2 h00 = __floats2half2_rn(wfun(S[t][j0][0]), wfun(S[t][j0][1]));
                    __half2 h01 = __floats2half2_rn(wfun(S[t][j0][2]), wfun(S[t][j0][3]));
                    __half2 h10 = __floats2half2_rn(wfun(S[t][j1][0]), wfun(S[t][j1][1]));
                    __half2 h11 = __floats2half2_rn(wfun(S[t][j1][2]), wfun(S[t][j1][3]));
                    float2 f;
                    f = __half22float2(h00); den[t][0] += f.x + f.y;
                    f = __half22float2(h01); den[t][1] += f.x + f.y;
                    f = __half22float2(h10); den[t][0] += f.x + f.y;
                    f = __half22float2(h11); den[t][1] += f.x + f.y;
                    Pf[t][0] = h2_as_u32(h00);   // a0: row g,   k 0-7
                    Pf[t][1] = h2_as_u32(h01);   // a1: row g+8, k 0-7
                    Pf[t][2] = h2_as_u32(h10);   // a2: row g,   k 8-15
                    Pf[t][3] = h2_as_u32(h11);   // a3: row g+8, k 8-15
                }
                const uint32_t cswX = (uint32_t)(((t2 * 2 + bhi) ^ xl) << 4);
#pragma unroll
                for (int cc = 0; cc < 8; cc++) {
                    uint32_t xb[4];
                    ldsm4(xb, xrow + cc * 16 * 128 + cswX);
                    mma16816(O[0][2 * cc],     Pf[0], xb[0], xb[1]);
                    mma16816(O[0][2 * cc + 1], Pf[0], xb[2], xb[3]);
                    mma16816(O[1][2 * cc],     Pf[1], xb[0], xb[1]);
                    mma16816(O[1][2 * cc + 1], Pf[1], xb[2], xb[3]);
                }
            }
        }

        __syncthreads();                  // all warps done with stage (j&1)
        if (j + 2 < NCHUNK) load_chunk(b, (j + 2) * KT, j & 1, sb, tid);
    }

    // ---- epilogue: quad-reduce denom, scale, store ----
#pragma unroll
    for (int t = 0; t < 2; t++) {
        float d0 = den[t][0], d1 = den[t][1];
        d0 += __shfl_xor_sync(0xffffffffu, d0, 1);
        d0 += __shfl_xor_sync(0xffffffffu, d0, 2);
        d1 += __shfl_xor_sync(0xffffffffu, d1, 1);
        d1 += __shfl_xor_sync(0xffffffffu, d1, 2);
        float inv0 = 1.0f / d0, inv1 = 1.0f / d1;

        int r0 = k0 + qb + t * 16 + (lane >> 2);
        int r1 = r0 + 8;
        float* o0 = out + ((size_t)(b * N_ + r0)) * D_ + (lane & 3) * 2;
        float* o1 = out + ((size_t)(b * N_ + r1)) * D_ + (lane & 3) * 2;
#pragma unroll
        for (int nt = 0; nt < 16; nt++) {
            *(float2*)(o0 + nt * 8) = make_float2(O[t][nt][0] * inv0, O[t][nt][1] * inv0);
            *(float2*)(o1 + nt * 8) = make_float2(O[t][nt][2] * inv1, O[t][nt][3] * inv1);
        }
    }
}

// ---------------- launch ----------------------------------------------------
extern "C" void kernel_launch(void* const* d_in, const int* in_sizes, int n_in,
                              void* d_out, int out_size) {
    const float* x  = (const float*)d_in[0];
    const float* e  = (const float*)d_in[1];
    const float* d  = (const float*)d_in[2];
    const float* W1 = (const float*)d_in[3];
    const float* W2 = (const float*)d_in[4];
    float* out = (float*)d_out;

    cudaFuncSetAttribute(attn_kernel, cudaFuncAttributeMaxDynamicSharedMemorySize, SMEM_TOTAL);

    prep_qk<<<QK_WARPS / 8, 256>>>(e, d, W1, W2);

    dim3 tg(N_ / 32, D_ / 32, B_);
    transpose_x<<<tg, dim3(32, 8)>>>(x);

    attn_kernel<<<dim3(N_ / MT, B_), 256, SMEM_TOTAL>>>(out);
}

// round 16
// speedup vs baseline: 1.7576x; 1.7576x over previous
#include <cuda_runtime.h>
#include <cuda_fp16.h>
#include <cstdint>

// ============================================================
// out[b,k,c] = softmax_m( tanh(e[b,m]·W1[k] + d[b,k]·W2[m]) ) · x[b,m,c]
// B=16, N=2048, D=128.
// Flash-style fused attention, mma.sync.m16n8k16 + ldmatrix + cp.async.
// tanh bounds scores in [-1,1] -> no online max rescaling needed.
// R15: attn = R12 verbatim (best proven, ~155us). Prep merged into ONE
//      launch: blocks [0,8192) build Qf/Kf (warp-coalesced), blocks
//      [8192,12288) transpose x -> XT with half2-packed writes (R13's
//      verified transpose). Cuts prep+launch overhead ~23us -> ~10us.
// ============================================================

#define DEVI __device__ __forceinline__

constexpr int B_ = 16, N_ = 2048, D_ = 128, F_ = 256;
constexpr int MT = 256;              // queries per CTA
constexpr int KT = 64;               // keys per chunk
constexpr int NCHUNK = N_ / KT;      // 32

// ---------------- device scratch -------------------------------------------
__device__ __half g_Qf[(size_t)B_ * N_ * F_];   // [b,k,256] = [W1[k] | d[b,k]]
__device__ __half g_Kf[(size_t)B_ * N_ * F_];   // [b,m,256] = [e[b,m] | W2[m]]
__device__ __half g_XT[(size_t)B_ * D_ * N_];   // [b,c,m]   = x[b,m,c]

// ---------------- SMEM layout (bytes), XOR-swizzled, no padding -------------
constexpr int SM_Q   = 0;
constexpr int QSIZE  = MT * 512;                // 131072
constexpr int KSTAGE = KT * 512;                // 32768
constexpr int SM_K   = SM_Q + QSIZE;
constexpr int XSTAGE = D_ * 128;                // 16384
constexpr int SM_X   = SM_K + 2 * KSTAGE;
constexpr int SMEM_TOTAL = SM_X + 2 * XSTAGE;   // 229376 (224 KB)

// ---------------- PTX helpers ----------------------------------------------
DEVI uint32_t smem_u32(const void* p) {
    uint32_t a;
    asm("{ .reg .u64 t; cvta.to.shared.u64 t, %1; cvt.u32.u64 %0, t; }" : "=r"(a) : "l"(p));
    return a;
}
DEVI float ex2f(float x) { float y; asm("ex2.approx.f32 %0,%1;" : "=f"(y) : "f"(x)); return y; }
DEVI float tanhf_hw(float x) { float y; asm("tanh.approx.f32 %0,%1;" : "=f"(y) : "f"(x)); return y; }

DEVI void cp_async16(uint32_t dst, const void* src) {
    asm volatile("cp.async.cg.shared.global [%0], [%1], 16;" :: "r"(dst), "l"(src) : "memory");
}
DEVI void cp_commit() { asm volatile("cp.async.commit_group;" ::: "memory"); }
DEVI void cp_wait0()  { asm volatile("cp.async.wait_group 0;" ::: "memory"); }
DEVI void cp_wait1()  { asm volatile("cp.async.wait_group 1;" ::: "memory"); }
DEVI void cp_wait2()  { asm volatile("cp.async.wait_group 2;" ::: "memory"); }

DEVI void ldsm4(uint32_t r[4], uint32_t addr) {
    asm volatile("ldmatrix.sync.aligned.m8n8.x4.shared.b16 {%0,%1,%2,%3}, [%4];"
                 : "=r"(r[0]), "=r"(r[1]), "=r"(r[2]), "=r"(r[3]) : "r"(addr));
}
DEVI void mma16816(float d[4], const uint32_t a[4], uint32_t b0, uint32_t b1) {
    asm volatile("mma.sync.aligned.m16n8k16.row.col.f32.f16.f16.f32 "
                 "{%0,%1,%2,%3}, {%4,%5,%6,%7}, {%8,%9}, {%0,%1,%2,%3};"
                 : "+f"(d[0]), "+f"(d[1]), "+f"(d[2]), "+f"(d[3])
                 : "r"(a[0]), "r"(a[1]), "r"(a[2]), "r"(a[3]), "r"(b0), "r"(b1));
}

DEVI uint32_t h2_as_u32(__half2 h) { uint32_t u; __builtin_memcpy(&u, &h, 4); return u; }

// w = exp(tanh(s) - 1) = 2^( log2e*(tanh(s) - 1) )   (shift-invariant weight)
DEVI float wfun(float s) {
    const float l2e = 1.4426950409f;
    float t = tanhf_hw(s);
    return ex2f(fmaf(t, l2e, -l2e));
}

// ---------------- merged prep: Qf/Kf build + X transpose, ONE launch --------
// Blocks [0, QK_BLOCKS): 8 warps each; warp w handles one 128-feat row half.
//   h=0: Qf[b,k,0:128]  = fp16(W1[k]),  Kf[b,k,0:128]  = fp16(e[b,k])
//   h=1: Qf[b,k,128:256]= fp16(d[b,k]), Kf[b,k,128:256]= fp16(W2[k])
// Blocks [QK_BLOCKS, QK_BLOCKS+XT_BLOCKS): 32x32 tile transpose of x into XT
//   with half2-packed (4B) stores, verified in R13.
constexpr int QK_WARPS  = B_ * N_ * 2;                    // 65536
constexpr int QK_BLOCKS = QK_WARPS / 8;                   // 8192
constexpr int XT_BLOCKS = (N_ / 32) * (D_ / 32) * B_;     // 4096
constexpr int PREP_BLOCKS = QK_BLOCKS + XT_BLOCKS;        // 12288

__global__ void prep_all(const float* __restrict__ e, const float* __restrict__ d,
                         const float* __restrict__ W1, const float* __restrict__ W2,
                         const float* __restrict__ x) {
    __shared__ float tile[32][33];
    int bid = blockIdx.x;
    if (bid < QK_BLOCKS) {
        int w    = bid * 8 + ((int)threadIdx.x >> 5);
        int lane = threadIdx.x & 31;
        int h = w & 1;
        int k = (w >> 1) & (N_ - 1);
        int b = w >> 12;
        const float4* qsrc;
        const float4* ksrc;
        if (h == 0) {
            qsrc = (const float4*)(W1 + (size_t)k * D_);
            ksrc = (const float4*)(e + ((size_t)(b * N_ + k)) * D_);
        } else {
            qsrc = (const float4*)(d + ((size_t)(b * N_ + k)) * D_);
            ksrc = (const float4*)(W2 + (size_t)k * D_);
        }
        float4 qv = qsrc[lane];
        float4 kv = ksrc[lane];
        uint2 qo = make_uint2(h2_as_u32(__floats2half2_rn(qv.x, qv.y)),
                              h2_as_u32(__floats2half2_rn(qv.z, qv.w)));
        uint2 ko = make_uint2(h2_as_u32(__floats2half2_rn(kv.x, kv.y)),
                              h2_as_u32(__floats2half2_rn(kv.z, kv.w)));
        size_t roff = ((size_t)(b * N_ + k)) * F_ + h * 128 + lane * 4;
        *(uint2*)(g_Qf + roff) = qo;
        *(uint2*)(g_Kf + roff) = ko;
    } else {
        int bid2 = bid - QK_BLOCKS;
        int m0 = (bid2 & 63) * 32;            // N_/32 = 64
        int c0 = ((bid2 >> 6) & 3) * 32;      // D_/32 = 4
        int b  = bid2 >> 8;                   // batch
        int tx = threadIdx.x & 31, ty = (int)threadIdx.x >> 5;   // ty: 0..7
#pragma unroll
        for (int i = 0; i < 4; i++)
            tile[ty + 8 * i][tx] = x[((size_t)(b * N_ + m0 + ty + 8 * i)) * D_ + c0 + tx];
        __syncthreads();
        int mp = tx & 15;         // m-pair index
        int hi = tx >> 4;
#pragma unroll
        for (int i = 0; i < 2; i++) {
            int c = i * 16 + ty * 2 + hi;
            uint32_t v = h2_as_u32(__floats2half2_rn(tile[2 * mp][c], tile[2 * mp + 1][c]));
            *(uint32_t*)(g_XT + ((size_t)(b * D_ + c0 + c)) * N_ + m0 + 2 * mp) = v;
        }
    }
}

// ---------------- chunk loader: K (64x256) + XT (128x64), swizzled ----------
DEVI void load_chunk(int b, int m0, int stage, uint32_t sb, int tid) {
    const uint32_t stK = sb + SM_K + stage * KSTAGE;
    const uint32_t stX = sb + SM_X + stage * XSTAGE;
    const __half* kbase = g_Kf + ((size_t)(b * N_ + m0)) * F_;
#pragma unroll
    for (int i = 0; i < 8; i++) {
        int lin = tid + i * 256;          // 0..2047
        int row = lin >> 5;               // 0..63
        int ch  = lin & 31;
        cp_async16(stK + row * 512 + ((ch ^ (row & 7)) << 4),
                   kbase + (size_t)row * F_ + ch * 8);
    }
    const __half* xbase = g_XT + (size_t)b * D_ * N_ + m0;
#pragma unroll
    for (int i = 0; i < 4; i++) {
        int lin = tid + i * 256;          // 0..1023
        int row = lin >> 3;               // c: 0..127
        int ch  = lin & 7;
        cp_async16(stX + row * 128 + ((ch ^ (row & 7)) << 4),
                   xbase + (size_t)row * N_ + ch * 8);
    }
    cp_commit();
}

// ---------------- main fused attention kernel (exact R8/R12) ----------------
__global__ void __launch_bounds__(256, 1) attn_kernel(float* __restrict__ out) {
    extern __shared__ __align__(1024) char smem[];
    const uint32_t sb = smem_u32(smem);
    const int tid = threadIdx.x;
    const int wid = tid >> 5;
    const int lane = tid & 31;
    const int b = blockIdx.y;
    const int k0 = blockIdx.x * MT;
    const int qb = wid * 32;             // this warp's 32 query rows (2 m-tiles)

    // ---- issue Q (group0), chunk0 (group1), chunk1 (group2) ----
    {
        const __half* qbase = g_Qf + ((size_t)(b * N_ + k0)) * F_;
#pragma unroll
        for (int i = 0; i < 32; i++) {
            int lin = tid + i * 256;      // 0..8191
            int row = lin >> 5;           // 0..255
            int ch  = lin & 31;
            cp_async16(sb + SM_Q + row * 512 + ((ch ^ (row & 7)) << 4),
                       qbase + (size_t)row * F_ + ch * 8);
        }
        cp_commit();
    }
    load_chunk(b, 0, 0, sb, tid);
    load_chunk(b, KT, 1, sb, tid);

    float O[2][16][4];
#pragma unroll
    for (int t = 0; t < 2; t++)
#pragma unroll
        for (int i = 0; i < 16; i++) { O[t][i][0] = O[t][i][1] = O[t][i][2] = O[t][i][3] = 0.f; }
    float den[2][2] = {{0.f, 0.f}, {0.f, 0.f}};

    // ldmatrix lane maps (verified R7+).
    // A (Q): row = lane&15, col-half = lane>>4.
    // B (K/X): row = (lane&7)+((lane>>4)<<3), col-half = (lane>>3)&1.
    const int arow = lane & 15;
    const int ahi  = lane >> 4;
    const int brow = (lane & 7) + ((lane >> 4) << 3);
    const int bhi  = (lane >> 3) & 1;
    const int xl   = lane & 7;           // row&7 for BOTH maps (tile bases %16==0)
    const uint32_t qrow0 = sb + SM_Q + (qb + arow) * 512;
    const uint32_t qrow1 = qrow0 + 16 * 512;

    cp_wait2();                           // Q group complete
    __syncthreads();

    for (int j = 0; j < NCHUNK; j++) {
        if (j + 1 < NCHUNK) cp_wait1(); else cp_wait0();
        __syncthreads();
        const uint32_t stK = sb + SM_K + (j & 1) * KSTAGE;
        const uint32_t stX = sb + SM_X + (j & 1) * XSTAGE;
        const uint32_t krow = stK + brow * 512;
        const uint32_t xrow = stX + brow * 128;

        // ---- QK: S[32 x 64] = Q @ Kchunk^T (2 m-tiles share every K frag) ----
        float S[2][8][4];
#pragma unroll
        for (int t = 0; t < 2; t++)
#pragma unroll
            for (int i = 0; i < 8; i++) { S[t][i][0] = S[t][i][1] = S[t][i][2] = S[t][i][3] = 0.f; }

#pragma unroll
        for (int kt = 0; kt < 16; kt++) {
            const uint32_t cswA = (uint32_t)(((kt * 2 + ahi) ^ xl) << 4);
            const uint32_t cswB = (uint32_t)(((kt * 2 + bhi) ^ xl) << 4);
            uint32_t qa0[4], qa1[4];
            ldsm4(qa0, qrow0 + cswA);
            ldsm4(qa1, qrow1 + cswA);
#pragma unroll
            for (int ng = 0; ng < 4; ng++) {
                uint32_t kb[4];
                ldsm4(kb, krow + ng * 16 * 512 + cswB);
                mma16816(S[0][2 * ng],     qa0, kb[0], kb[1]);
                mma16816(S[0][2 * ng + 1], qa0, kb[2], kb[3]);
                mma16816(S[1][2 * ng],     qa1, kb[0], kb[1]);
                mma16816(S[1][2 * ng + 1], qa1, kb[2], kb[3]);
            }
        }

        // ---- per t2-group: weights (tanh.approx + ex2) -> pack -> PV mma ----
#pragma unroll
        for (int t2 = 0; t2 < 4; t2++) {
            uint32_t Pf[2][4];
#pragma unroll
            for (int t = 0; t < 2; t++) {
                int j0 = 2 * t2, j1 = 2 * t2 + 1;
                __half2 h00 = __floats2half2_rn(wfun(S[t][j0][0]), wfun(S[t][j0][1]));
                __half2 h01 = __floats2half2_rn(wfun(S[t][j0][2]), wfun(S[t][j0][3]));
                __half2 h10 = __floats2half2_rn(wfun(S[t][j1][0]), wfun(S[t][j1][1]));
                __half2 h11 = __floats2half2_rn(wfun(S[t][j1][2]), wfun(S[t][j1][3]));
                float2 f;
                f = __half22float2(h00); den[t][0] += f.x + f.y;
                f = __half22float2(h01); den[t][1] += f.x + f.y;
                f = __half22float2(h10); den[t][0] += f.x + f.y;
                f = __half22float2(h11); den[t][1] += f.x + f.y;
                Pf[t][0] = h2_as_u32(h00);   // a0: row g,   k 0-7  of this 16-key tile
                Pf[t][1] = h2_as_u32(h01);   // a1: row g+8, k 0-7
                Pf[t][2] = h2_as_u32(h10);   // a2: row g,   k 8-15
                Pf[t][3] = h2_as_u32(h11);   // a3: row g+8, k 8-15
            }
            const uint32_t cswB = (uint32_t)(((t2 * 2 + bhi) ^ xl) << 4);
#pragma unroll
            for (int cc = 0; cc < 8; cc++) {
                uint32_t xb[4];
                ldsm4(xb, xrow + cc * 16 * 128 + cswB);
                mma16816(O[0][2 * cc],     Pf[0], xb[0], xb[1]);
                mma16816(O[0][2 * cc + 1], Pf[0], xb[2], xb[3]);
                mma16816(O[1][2 * cc],     Pf[1], xb[0], xb[1]);
                mma16816(O[1][2 * cc + 1], Pf[1], xb[2], xb[3]);
            }
        }

        __syncthreads();                  // all warps done with stage (j&1)
        if (j + 2 < NCHUNK) load_chunk(b, (j + 2) * KT, j & 1, sb, tid);
    }

    // ---- epilogue: quad-reduce denom, scale, store ----
#pragma unroll
    for (int t = 0; t < 2; t++) {
        float d0 = den[t][0], d1 = den[t][1];
        d0 += __shfl_xor_sync(0xffffffffu, d0, 1);
        d0 += __shfl_xor_sync(0xffffffffu, d0, 2);
        d1 += __shfl_xor_sync(0xffffffffu, d1, 1);
        d1 += __shfl_xor_sync(0xffffffffu, d1, 2);
        float inv0 = 1.0f / d0, inv1 = 1.0f / d1;

        int r0 = k0 + qb + t * 16 + (lane >> 2);
        int r1 = r0 + 8;
        float* o0 = out + ((size_t)(b * N_ + r0)) * D_ + (lane & 3) * 2;
        float* o1 = out + ((size_t)(b * N_ + r1)) * D_ + (lane & 3) * 2;
#pragma unroll
        for (int nt = 0; nt < 16; nt++) {
            *(float2*)(o0 + nt * 8) = make_float2(O[t][nt][0] * inv0, O[t][nt][1] * inv0);
            *(float2*)(o1 + nt * 8) = make_float2(O[t][nt][2] * inv1, O[t][nt][3] * inv1);
        }
    }
}

// ---------------- launch ----------------------------------------------------
extern "C" void kernel_launch(void* const* d_in, const int* in_sizes, int n_in,
                              void* d_out, int out_size) {
    const float* x  = (const float*)d_in[0];
    const float* e  = (const float*)d_in[1];
    const float* d  = (const float*)d_in[2];
    const float* W1 = (const float*)d_in[3];
    const float* W2 = (const float*)d_in[4];
    float* out = (float*)d_out;

    cudaFuncSetAttribute(attn_kernel, cudaFuncAttributeMaxDynamicSharedMemorySize, SMEM_TOTAL);

    prep_all<<<PREP_BLOCKS, 256>>>(e, d, W1, W2, x);

    attn_kernel<<<dim3(N_ / MT, B_), 256, SMEM_TOTAL>>>(out);
}